// round 2
// baseline (speedup 1.0000x reference)
#include <cuda_runtime.h>

#define DSZ   160
#define D2    (DSZ * DSZ)
#define NVOX  (DSZ * DSZ * DSZ)
#define BIGL  (NVOX + 2)
#define NBINS 4096
#define HALFW 16
#define WINW  32
#define KCCL  16

// ---------------- static device scratch (no allocations allowed) ----------------
__device__ int            g_labA[NVOX];
__device__ int            g_labB[NVOX];
__device__ int            g_cnt[NVOX + 1];
__device__ int            g_ibufA[NVOX];
__device__ int            g_ibufB[NVOX];
__device__ int            g_cw[NVOX];       // counts_window (exact integer)
__device__ float          g_cs[NVOX];       // counts_size (float, from int64)
__device__ float          g_mean1[NVOX];
__device__ unsigned char  g_valid1[NVOX];
__device__ unsigned char  g_vsum[NVOX];
__device__ unsigned short g_bin[NVOX];
__device__ int            g_hist[NBINS];
__device__ float          g_ph[NBINS];
__device__ double         g_T[1];

// ---------------- init labels: seg ? linear+1 : BIG ----------------
__global__ void k_init_labels(const float* __restrict__ data, float v) {
    int x = blockIdx.x * blockDim.x + threadIdx.x;
    if (x < NVOX) {
        float r = rintf(data[x]);
        g_labA[x] = (r == v) ? (x + 1) : BIGL;
    }
}

// ---------------- one Jacobi min-propagation sweep (6-neighborhood) ----------------
__global__ void __launch_bounds__(512) k_sweep(int parity) {
    const int* __restrict__ A = parity ? g_labB : g_labA;
    int*       __restrict__ B = parity ? g_labA : g_labB;
    int k = blockIdx.x * 32 + threadIdx.x;
    int j = blockIdx.y * 4  + threadIdx.y;
    int i = blockIdx.z * 4  + threadIdx.z;
    int x = (i * DSZ + j) * DSZ + k;
    int c = A[x];
    if (c == BIGL) { B[x] = BIGL; return; }
    int m = c;
    if (k > 0)       m = min(m, A[x - 1]);
    if (k < DSZ - 1) m = min(m, A[x + 1]);
    if (j > 0)       m = min(m, A[x - DSZ]);
    if (j < DSZ - 1) m = min(m, A[x + DSZ]);
    if (i > 0)       m = min(m, A[x - D2]);
    if (i < DSZ - 1) m = min(m, A[x + D2]);
    B[x] = m;
}

// ---------------- zero component counters ----------------
__global__ void k_zero_cnt() {
    int stride = gridDim.x * blockDim.x;
    for (int x = blockIdx.x * blockDim.x + threadIdx.x; x < NVOX + 1; x += stride)
        g_cnt[x] = 0;
}

// ---------------- component size count (warp-aggregated atomics) ----------------
__global__ void k_count() {
    int x = blockIdx.x * blockDim.x + threadIdx.x;
    if (x >= NVOX) return;
    int l = g_labA[x];
    unsigned mask = __activemask();
    unsigned grp  = __match_any_sync(mask, l);
    int leader = __ffs(grp) - 1;
    if (l != BIGL && (int)(threadIdx.x & 31) == leader)
        atomicAdd(&g_cnt[l], __popc(grp));
}

// ---------------- seg indicator -> ibufA (int 0/1) ----------------
__global__ void k_segf() {
    int x = blockIdx.x * blockDim.x + threadIdx.x;
    if (x < NVOX) g_ibufA[x] = (g_labA[x] != BIGL) ? 1 : 0;
}

// ---------------- box pass along k (contiguous axis): ibufA -> ibufB, int ----------------
__global__ void __launch_bounds__(DSZ) k_boxX() {
    __shared__ int s[DSZ];
    int line = blockIdx.x;          // i*DSZ + j
    int t    = threadIdx.x;
    int base = line * DSZ;
    s[t] = g_ibufA[base + t];
    __syncthreads();
    int lo = t - HALFW;     if (lo < 0) lo = 0;
    int hi = t + HALFW - 1; if (hi > DSZ - 1) hi = DSZ - 1;
    int acc = 0;
    #pragma unroll 4
    for (int u = lo; u <= hi; ++u) acc += s[u];
    g_ibufB[base + t] = acc;
}

// ---------------- box pass along j: ibufB -> ibufA, int ----------------
__global__ void __launch_bounds__(512) k_boxY() {
    __shared__ int s[DSZ][33];
    int kk = threadIdx.x;
    int jj = threadIdx.y;
    int k  = blockIdx.x * 32 + kk;
    int i  = blockIdx.y;
    int base = i * D2 + k;
    for (int j = jj; j < DSZ; j += 16)
        s[j][kk] = g_ibufB[base + j * DSZ];
    __syncthreads();
    for (int j = jj; j < DSZ; j += 16) {
        int lo = j - HALFW;     if (lo < 0) lo = 0;
        int hi = j + HALFW - 1; if (hi > DSZ - 1) hi = DSZ - 1;
        int acc = 0;
        #pragma unroll 4
        for (int t = lo; t <= hi; ++t) acc += s[t][kk];
        g_ibufA[base + j * DSZ] = acc;
    }
}

// ---------------- box pass along i (cw): ibufA -> g_cw, int (max 32768, exact) ----------------
__global__ void __launch_bounds__(512) k_boxZ_cw() {
    __shared__ int s[DSZ][33];
    int kk = threadIdx.x;
    int ii = threadIdx.y;
    int k  = blockIdx.x * 32 + kk;
    int j  = blockIdx.y;
    int base = j * DSZ + k;
    for (int i = ii; i < DSZ; i += 16)
        s[i][kk] = g_ibufA[base + i * D2];
    __syncthreads();
    for (int i = ii; i < DSZ; i += 16) {
        int lo = i - HALFW;     if (lo < 0) lo = 0;
        int hi = i + HALFW - 1; if (hi > DSZ - 1) hi = DSZ - 1;
        int acc = 0;
        #pragma unroll 4
        for (int t = lo; t <= hi; ++t) acc += s[t][kk];
        g_cw[base + i * D2] = acc;
    }
}

// ---------------- box pass along i (cs): ibufA -> g_cs, int64 accum -> float ----------------
__global__ void __launch_bounds__(512) k_boxZ_cs() {
    __shared__ int s[DSZ][33];
    int kk = threadIdx.x;
    int ii = threadIdx.y;
    int k  = blockIdx.x * 32 + kk;
    int j  = blockIdx.y;
    int base = j * DSZ + k;
    for (int i = ii; i < DSZ; i += 16)
        s[i][kk] = g_ibufA[base + i * D2];
    __syncthreads();
    for (int i = ii; i < DSZ; i += 16) {
        int lo = i - HALFW;     if (lo < 0) lo = 0;
        int hi = i + HALFW - 1; if (hi > DSZ - 1) hi = DSZ - 1;
        long long acc = 0;
        #pragma unroll 4
        for (int t = lo; t <= hi; ++t) acc += (long long)s[t][kk];
        g_cs[base + i * D2] = (float)acc;
    }
}

// ---------------- lsize*valid -> ibufA (int) ; record valid per mode ----------------
// Axis-sum bounds: lsize*valid <= ~4.1M; after k: <=32*4.1M=1.3e8 (int ok);
// after j: <=32*1.3e8=4.2e9 -> EXCEEDS int32. So k/j passes on cs must be careful.
// Max component size is bounded by count of that value ~ NVOX/3 = 1.37e6.
// After k: 32*1.37e6 = 4.4e7 (ok). After j: 32*4.4e7 = 1.4e9 < 2^31 (ok).
// After i: up to 4.5e10 -> int64 in k_boxZ_cs. Worst case all NVOX one comp:
// 4.1e6 -> k: 1.3e8 ok; j: 4.2e9 OVERFLOW. But then seg is everything and
// comp size = NVOX=4.096e6: j-sum = 32*32*4.096e6 = 4.19e9 > 2^31. Guard: use
// unsigned int for j pass (max 4.3e9 fits) — wraps only above 4.29e9, and the
// absolute max possible is 1024*NVOX = 4.194e9 < 4.295e9. Safe.
__global__ void k_lsv(int mode) {
    int x = blockIdx.x * blockDim.x + threadIdx.x;
    if (x >= NVOX) return;
    int cw = g_cw[x];
    unsigned char valid = (cw > 100) ? 1 : 0;
    int l = g_labA[x];
    g_ibufA[x] = (l != BIGL && valid) ? g_cnt[l] : 0;
    if (mode == 0)      g_vsum[x]   = valid;
    else if (mode == 2) g_vsum[x]   = (unsigned char)(g_vsum[x] + valid);
    else                g_valid1[x] = valid;
}

// ---------------- j pass for cs path with unsigned accum (see bound note) ----------------
__global__ void __launch_bounds__(512) k_boxY_u() {
    __shared__ unsigned s[DSZ][33];
    int kk = threadIdx.x;
    int jj = threadIdx.y;
    int k  = blockIdx.x * 32 + kk;
    int i  = blockIdx.y;
    int base = i * D2 + k;
    for (int j = jj; j < DSZ; j += 16)
        s[j][kk] = (unsigned)g_ibufB[base + j * DSZ];
    __syncthreads();
    for (int j = jj; j < DSZ; j += 16) {
        int lo = j - HALFW;     if (lo < 0) lo = 0;
        int hi = j + HALFW - 1; if (hi > DSZ - 1) hi = DSZ - 1;
        unsigned acc = 0;
        #pragma unroll 4
        for (int t = lo; t <= hi; ++t) acc += s[t][kk];
        g_ibufA[base + j * DSZ] = (int)acc;   // reinterpreted in k_boxZ_cs_u
    }
}

// i pass for cs reading unsigned-encoded ints
__global__ void __launch_bounds__(512) k_boxZ_cs_u() {
    __shared__ unsigned s[DSZ][33];
    int kk = threadIdx.x;
    int ii = threadIdx.y;
    int k  = blockIdx.x * 32 + kk;
    int j  = blockIdx.y;
    int base = j * DSZ + k;
    for (int i = ii; i < DSZ; i += 16)
        s[i][kk] = (unsigned)g_ibufA[base + i * D2];
    __syncthreads();
    for (int i = ii; i < DSZ; i += 16) {
        int lo = i - HALFW;     if (lo < 0) lo = 0;
        int hi = i + HALFW - 1; if (hi > DSZ - 1) hi = DSZ - 1;
        unsigned long long acc = 0;
        #pragma unroll 4
        for (int t = lo; t <= hi; ++t) acc += (unsigned long long)s[t][kk];
        g_cs[base + i * D2] = (float)acc;
    }
}

// ---------------- mean = cw>0 ? cs/cw : 0 ----------------
__global__ void k_mean() {
    int x = blockIdx.x * blockDim.x + threadIdx.x;
    if (x >= NVOX) return;
    int cw = g_cw[x];
    g_mean1[x] = (cw > 0) ? (g_cs[x] / (float)cw) : 0.0f;
}

// ---------------- candidates + bin index ----------------
__global__ void k_candbin(float* __restrict__ out) {
    int x = blockIdx.x * blockDim.x + threadIdx.x;
    if (x >= NVOX) return;
    int k = x % DSZ;
    int j = (x / DSZ) % DSZ;
    int i = x / D2;
    bool interior = (i >= HALFW) && (i < DSZ - HALFW) &&
                    (j >= HALFW) && (j < DSZ - HALFW) &&
                    (k >= HALFW) && (k < DSZ - HALFW);
    int fin = (interior ? (int)g_valid1[x] : 0) + (int)g_vsum[x];
    int cand = (fin >= 2) ? 1 : 0;
    out[x] = (float)cand;
    float poss = cand ? g_mean1[x] : 0.0f;
    float r = rintf(poss);          // round-half-to-even, matches jnp.round
    int b = (r <= 0.0f) ? 0 : ((r >= 4095.0f) ? 4095 : (int)r);
    g_bin[x] = (unsigned short)b;
}

// ---------------- zero histogram + grand total ----------------
__global__ void k_zero_hist() {
    int x = blockIdx.x * blockDim.x + threadIdx.x;
    if (x < NBINS) g_hist[x] = 0;
    if (x == 0) g_T[0] = 0.0;
}

// ---------------- histogram (shared + warp-aggregated) ----------------
__global__ void __launch_bounds__(256) k_hist() {
    __shared__ int sh[NBINS];
    for (int b = threadIdx.x; b < NBINS; b += blockDim.x) sh[b] = 0;
    __syncthreads();
    int stride = gridDim.x * blockDim.x;
    for (int x = blockIdx.x * blockDim.x + threadIdx.x; x < NVOX; x += stride) {
        int b = g_bin[x];
        unsigned mask = __activemask();
        unsigned grp  = __match_any_sync(mask, b);
        int leader = __ffs(grp) - 1;
        if ((int)(threadIdx.x & 31) == leader)
            atomicAdd(&sh[b], __popc(grp));
    }
    __syncthreads();
    for (int b = threadIdx.x; b < NBINS; b += blockDim.x) {
        int c = sh[b];
        if (c) atomicAdd(&g_hist[b], c);
    }
}

// ---------------- reciprocal-histogram weights (single block) ----------------
__global__ void __launch_bounds__(1024) k_weights() {
    __shared__ double sh[40];
    int tid  = threadIdx.x;
    int lane = tid & 31;
    int w    = tid >> 5;

    // numb = sum(hist[1:])
    double loc = 0.0;
    for (int b = tid; b < NBINS; b += 1024)
        if (b >= 1) loc += (double)g_hist[b];
    for (int o = 16; o; o >>= 1) loc += __shfl_down_sync(0xffffffffu, loc, o);
    if (lane == 0) sh[w] = loc;
    __syncthreads();
    if (w == 0) {
        double t = (lane < 32) ? sh[lane] : 0.0;
        for (int o = 16; o; o >>= 1) t += __shfl_down_sync(0xffffffffu, t, o);
        if (lane == 0) sh[33] = t;
    }
    __syncthreads();
    float numbf = (float)sh[33];
    __syncthreads();

    // rec and S = sum(rec)
    double locS = 0.0;
    for (int b = tid; b < NBINS; b += 1024) {
        float rec = 0.0f;
        if (b >= 1) {
            int h = g_hist[b];
            if (h > 0) rec = numbf / (float)h;
        }
        g_ph[b] = rec;
        locS += (double)rec;
    }
    for (int o = 16; o; o >>= 1) locS += __shfl_down_sync(0xffffffffu, locS, o);
    if (lane == 0) sh[w] = locS;
    __syncthreads();
    if (w == 0) {
        double t = (lane < 32) ? sh[lane] : 0.0;
        for (int o = 16; o; o >>= 1) t += __shfl_down_sync(0xffffffffu, t, o);
        if (lane == 0) sh[34] = t;
    }
    __syncthreads();
    float Sf = (float)sh[34];

    for (int b = tid; b < NBINS; b += 1024)
        g_ph[b] = g_ph[b] / Sf;     // ph[0] = 0/S = 0
}

// ---------------- total pw sum ----------------
__global__ void __launch_bounds__(256) k_sumT() {
    int stride = gridDim.x * blockDim.x;
    double loc = 0.0;
    for (int x = blockIdx.x * blockDim.x + threadIdx.x; x < NVOX; x += stride)
        loc += (double)g_ph[g_bin[x]];
    for (int o = 16; o; o >>= 1) loc += __shfl_down_sync(0xffffffffu, loc, o);
    __shared__ double sh[8];
    int lane = threadIdx.x & 31, w = threadIdx.x >> 5;
    if (lane == 0) sh[w] = loc;
    __syncthreads();
    if (w == 0) {
        double t = (lane < 8) ? sh[lane] : 0.0;
        for (int o = 16; o; o >>= 1) t += __shfl_down_sync(0xffffffffu, t, o);
        if (lane == 0) atomicAdd(&g_T[0], t);
    }
}

// ---------------- finalize proba ----------------
__global__ void k_final(float* __restrict__ out) {
    int x = blockIdx.x * blockDim.x + threadIdx.x;
    if (x >= NVOX) return;
    float T = (float)g_T[0];
    out[NVOX + x] = g_ph[g_bin[x]] / T;
}

// ---------------- host orchestration ----------------
extern "C" void kernel_launch(void* const* d_in, const int* in_sizes, int n_in,
                              void* d_out, int out_size) {
    (void)in_sizes; (void)n_in; (void)out_size;
    const float* data = (const float*)d_in[0];
    float* out = (float*)d_out;

    const int TPB = 256;
    const int NB  = (NVOX + TPB - 1) / TPB;   // 16000
    dim3 bSweep(32, 4, 4), gSweep(DSZ / 32, DSZ / 4, DSZ / 4);
    dim3 bTile(32, 16), gTile(DSZ / 32, DSZ);

    for (int v = 0; v < 3; ++v) {
        // CCL: init + 16 Jacobi sweeps (final labels land back in g_labA)
        k_init_labels<<<NB, TPB>>>(data, (float)v);
        for (int t = 0; t < KCCL; ++t)
            k_sweep<<<gSweep, bSweep>>>(t & 1);

        // component sizes
        k_zero_cnt<<<1024, 256>>>();
        k_count<<<NB, TPB>>>();

        // counts_window = box_sum(segf)  (all-integer, exact)
        k_segf<<<NB, TPB>>>();
        k_boxX<<<D2, DSZ>>>();
        k_boxY<<<gTile, bTile>>>();
        k_boxZ_cw<<<gTile, bTile>>>();        // -> g_cw (int)

        // counts_size = box_sum(lsize * valid); record valid mask
        k_lsv<<<NB, TPB>>>(v);
        k_boxX<<<D2, DSZ>>>();
        k_boxY_u<<<gTile, bTile>>>();
        k_boxZ_cs_u<<<gTile, bTile>>>();      // -> g_cs (float from int64)

        if (v == 1)
            k_mean<<<NB, TPB>>>();
    }

    // candidates + bins
    k_candbin<<<NB, TPB>>>(out);

    // probability weights
    k_zero_hist<<<(NBINS + 255) / 256, 256>>>();
    k_hist<<<1024, 256>>>();
    k_weights<<<1, 1024>>>();
    k_sumT<<<1024, 256>>>();
    k_final<<<NB, TPB>>>(out);
}

// round 3
// speedup vs baseline: 1.1084x; 1.1084x over previous
#include <cuda_runtime.h>

#define DSZ   160
#define D2    (DSZ * DSZ)
#define NVOX  (DSZ * DSZ * DSZ)
#define BIGL  (NVOX + 2)
#define NBINS 4096
#define HALFW 16
#define KCCL  16

// fused-sweep tile geometry
#define TK 32
#define TJ 16
#define TI 16
#define HALO 4
#define RK (TK + 2*HALO)   // 40
#define RJ (TJ + 2*HALO)   // 24
#define RI (TI + 2*HALO)   // 24
#define RKP 41             // padded k-stride (gcd(41,32)=1 -> conflict-free)
#define SWEEP_THREADS (RJ * RI)          // 576
#define SWEEP_SMEM (RI * RJ * RKP * 4)   // 94464 B

// ---------------- static device scratch ----------------
__device__ int            g_labA[NVOX];
__device__ int            g_labB[NVOX];
__device__ int            g_cnt[NVOX + 1];
__device__ int            g_ibufA[NVOX];
__device__ int            g_ibufB[NVOX];
__device__ int            g_cw[NVOX];
__device__ float          g_cs[NVOX];
__device__ float          g_mean1[NVOX];
__device__ unsigned char  g_valid1[NVOX];
__device__ unsigned char  g_vsum[NVOX];
__device__ unsigned short g_bin[NVOX];
__device__ int            g_hist[NBINS];
__device__ float          g_ph[NBINS];
__device__ double         g_T[1];

// ---------------- fused 4-sweep min-propagation (halo-4 tile) ----------------
// init!=0: labels computed from data on the fly (sweep-launch #1 of each value).
__global__ void __launch_bounds__(SWEEP_THREADS)
k_sweep4(const int* __restrict__ A, int* __restrict__ B,
         const float* __restrict__ data, float v, int initFlag) {
    extern __shared__ int s[];   // [RI][RJ][RKP]
    const int tid = threadIdx.x;
    const int tj = tid % RJ;         // 0..23
    const int ti = tid / RJ;         // 0..23
    const int k0 = blockIdx.x * TK;  // interior origin
    const int j0 = blockIdx.y * TJ;
    const int i0 = blockIdx.z * TI;

    // ---- load: one region row (ri=ti, rj=tj) of RK k-values per thread ----
    {
        const int gj = j0 + tj - HALO;
        const int gi = i0 + ti - HALO;
        const int gk0 = k0 - HALO;
        int* row = &s[(ti * RJ + tj) * RKP];
        const bool rowIn = (gj >= 0) & (gj < DSZ) & (gi >= 0) & (gi < DSZ);
        if (rowIn && gk0 >= 0 && gk0 + RK <= DSZ) {
            const int gbase = (gi * DSZ + gj) * DSZ + gk0;
            if (initFlag) {
                #pragma unroll
                for (int q = 0; q < RK / 4; ++q) {
                    const float4 d = *reinterpret_cast<const float4*>(&data[gbase + q * 4]);
                    row[q*4+0] = (rintf(d.x) == v) ? (gbase + q*4 + 1) : BIGL;
                    row[q*4+1] = (rintf(d.y) == v) ? (gbase + q*4 + 2) : BIGL;
                    row[q*4+2] = (rintf(d.z) == v) ? (gbase + q*4 + 3) : BIGL;
                    row[q*4+3] = (rintf(d.w) == v) ? (gbase + q*4 + 4) : BIGL;
                }
            } else {
                #pragma unroll
                for (int q = 0; q < RK / 4; ++q) {
                    const int4 d = *reinterpret_cast<const int4*>(&A[gbase + q * 4]);
                    row[q*4+0] = d.x; row[q*4+1] = d.y;
                    row[q*4+2] = d.z; row[q*4+3] = d.w;
                }
            }
        } else {
            for (int rk = 0; rk < RK; ++rk) {
                const int gk = gk0 + rk;
                int val = BIGL;
                if (rowIn && gk >= 0 && gk < DSZ) {
                    const int g = (gi * DSZ + gj) * DSZ + gk;
                    if (initFlag) val = (rintf(data[g]) == v) ? (g + 1) : BIGL;
                    else          val = A[g];
                }
                row[rk] = val;
            }
        }
    }

    // ---- 4 Jacobi min-propagation iterations in shared memory ----
    int* myrow = &s[(ti * RJ + tj) * RKP];
    const int* rowJm = (tj > 0)      ? &s[(ti * RJ + tj - 1) * RKP]  : 0;
    const int* rowJp = (tj < RJ - 1) ? &s[(ti * RJ + tj + 1) * RKP]  : 0;
    const int* rowIm = (ti > 0)      ? &s[((ti - 1) * RJ + tj) * RKP] : 0;
    const int* rowIp = (ti < RI - 1) ? &s[((ti + 1) * RJ + tj) * RKP] : 0;

    int nv[RK];
    #pragma unroll
    for (int t = 0; t < 4; ++t) {
        __syncthreads();
        int prev = BIGL;
        int cur  = myrow[0];
        #pragma unroll
        for (int kk = 0; kk < RK; ++kk) {
            const int nxt = (kk + 1 < RK) ? myrow[kk + 1] : BIGL;
            int m = BIGL;
            if (cur != BIGL) {
                m = min(cur, min(prev, nxt));
                if (rowJm) m = min(m, rowJm[kk]);
                if (rowJp) m = min(m, rowJp[kk]);
                if (rowIm) m = min(m, rowIm[kk]);
                if (rowIp) m = min(m, rowIp[kk]);
            }
            nv[kk] = m;
            prev = cur; cur = nxt;
        }
        __syncthreads();
        #pragma unroll
        for (int kk = 0; kk < RK; ++kk) myrow[kk] = nv[kk];
    }
    __syncthreads();

    // ---- store interior (exactly tiles the volume; int4) ----
    if (tj >= HALO && tj < RJ - HALO && ti >= HALO && ti < RI - HALO) {
        const int gj = j0 + tj - HALO;
        const int gi = i0 + ti - HALO;
        const int gbase = (gi * DSZ + gj) * DSZ + k0;
        #pragma unroll
        for (int q = 0; q < TK / 4; ++q) {
            int4 d;
            d.x = myrow[HALO + q*4 + 0];
            d.y = myrow[HALO + q*4 + 1];
            d.z = myrow[HALO + q*4 + 2];
            d.w = myrow[HALO + q*4 + 3];
            *reinterpret_cast<int4*>(&B[gbase + q * 4]) = d;
        }
    }
}

// ---------------- zero component counters ----------------
__global__ void k_zero_cnt() {
    int stride = gridDim.x * blockDim.x;
    for (int x = blockIdx.x * blockDim.x + threadIdx.x; x < NVOX + 1; x += stride)
        g_cnt[x] = 0;
}

// ---------------- component size count (warp-aggregated atomics) ----------------
__global__ void k_count() {
    int x = blockIdx.x * blockDim.x + threadIdx.x;
    if (x >= NVOX) return;
    int l = g_labA[x];
    unsigned mask = __activemask();
    unsigned grp  = __match_any_sync(mask, l);
    int leader = __ffs(grp) - 1;
    if (l != BIGL && (int)(threadIdx.x & 31) == leader)
        atomicAdd(&g_cnt[l], __popc(grp));
}

// ---------------- box pass along k, seg indicator fused: labA -> ibufB ----------------
__global__ void __launch_bounds__(DSZ) k_boxX_seg() {
    __shared__ int s[DSZ];
    int line = blockIdx.x;
    int t    = threadIdx.x;
    int base = line * DSZ;
    s[t] = (g_labA[base + t] != BIGL) ? 1 : 0;
    __syncthreads();
    int lo = t - HALFW;     if (lo < 0) lo = 0;
    int hi = t + HALFW - 1; if (hi > DSZ - 1) hi = DSZ - 1;
    int acc = 0;
    #pragma unroll 4
    for (int u = lo; u <= hi; ++u) acc += s[u];
    g_ibufB[base + t] = acc;
}

// ---------------- box pass along k: ibufA -> ibufB ----------------
__global__ void __launch_bounds__(DSZ) k_boxX() {
    __shared__ int s[DSZ];
    int line = blockIdx.x;
    int t    = threadIdx.x;
    int base = line * DSZ;
    s[t] = g_ibufA[base + t];
    __syncthreads();
    int lo = t - HALFW;     if (lo < 0) lo = 0;
    int hi = t + HALFW - 1; if (hi > DSZ - 1) hi = DSZ - 1;
    int acc = 0;
    #pragma unroll 4
    for (int u = lo; u <= hi; ++u) acc += s[u];
    g_ibufB[base + t] = acc;
}

// ---------------- box pass along j: ibufB -> ibufA (unsigned accum: max < 2^32) ----------------
__global__ void __launch_bounds__(512) k_boxY() {
    __shared__ unsigned s[DSZ][33];
    int kk = threadIdx.x;
    int jj = threadIdx.y;
    int k  = blockIdx.x * 32 + kk;
    int i  = blockIdx.y;
    int base = i * D2 + k;
    for (int j = jj; j < DSZ; j += 16)
        s[j][kk] = (unsigned)g_ibufB[base + j * DSZ];
    __syncthreads();
    for (int j = jj; j < DSZ; j += 16) {
        int lo = j - HALFW;     if (lo < 0) lo = 0;
        int hi = j + HALFW - 1; if (hi > DSZ - 1) hi = DSZ - 1;
        unsigned acc = 0;
        #pragma unroll 4
        for (int t = lo; t <= hi; ++t) acc += s[t][kk];
        g_ibufA[base + j * DSZ] = (int)acc;
    }
}

// ---------------- box pass along i (cw): ibufA -> g_cw (int, max 32768) ----------------
__global__ void __launch_bounds__(512) k_boxZ_cw() {
    __shared__ int s[DSZ][33];
    int kk = threadIdx.x;
    int ii = threadIdx.y;
    int k  = blockIdx.x * 32 + kk;
    int j  = blockIdx.y;
    int base = j * DSZ + k;
    for (int i = ii; i < DSZ; i += 16)
        s[i][kk] = g_ibufA[base + i * D2];
    __syncthreads();
    for (int i = ii; i < DSZ; i += 16) {
        int lo = i - HALFW;     if (lo < 0) lo = 0;
        int hi = i + HALFW - 1; if (hi > DSZ - 1) hi = DSZ - 1;
        int acc = 0;
        #pragma unroll 4
        for (int t = lo; t <= hi; ++t) acc += s[t][kk];
        g_cw[base + i * D2] = acc;
    }
}

// ---------------- box pass along i (cs): ibufA(u32) -> g_cs (u64 accum -> float) ----------------
__global__ void __launch_bounds__(512) k_boxZ_cs() {
    __shared__ unsigned s[DSZ][33];
    int kk = threadIdx.x;
    int ii = threadIdx.y;
    int k  = blockIdx.x * 32 + kk;
    int j  = blockIdx.y;
    int base = j * DSZ + k;
    for (int i = ii; i < DSZ; i += 16)
        s[i][kk] = (unsigned)g_ibufA[base + i * D2];
    __syncthreads();
    for (int i = ii; i < DSZ; i += 16) {
        int lo = i - HALFW;     if (lo < 0) lo = 0;
        int hi = i + HALFW - 1; if (hi > DSZ - 1) hi = DSZ - 1;
        unsigned long long acc = 0;
        #pragma unroll 4
        for (int t = lo; t <= hi; ++t) acc += (unsigned long long)s[t][kk];
        g_cs[base + i * D2] = (float)acc;
    }
}

// ---------------- lsize*valid -> ibufA ; record valid per mode ----------------
__global__ void k_lsv(int mode) {
    int x = blockIdx.x * blockDim.x + threadIdx.x;
    if (x >= NVOX) return;
    int cw = g_cw[x];
    unsigned char valid = (cw > 100) ? 1 : 0;
    int l = g_labA[x];
    g_ibufA[x] = (l != BIGL && valid) ? g_cnt[l] : 0;
    if (mode == 0)      g_vsum[x]   = valid;
    else if (mode == 2) g_vsum[x]   = (unsigned char)(g_vsum[x] + valid);
    else                g_valid1[x] = valid;
}

// ---------------- mean = cw>0 ? cs/cw : 0 ----------------
__global__ void k_mean() {
    int x = blockIdx.x * blockDim.x + threadIdx.x;
    if (x >= NVOX) return;
    int cw = g_cw[x];
    g_mean1[x] = (cw > 0) ? (g_cs[x] / (float)cw) : 0.0f;
}

// ---------------- candidates + bin index ----------------
__global__ void k_candbin(float* __restrict__ out) {
    int x = blockIdx.x * blockDim.x + threadIdx.x;
    if (x >= NVOX) return;
    int k = x % DSZ;
    int j = (x / DSZ) % DSZ;
    int i = x / D2;
    bool interior = (i >= HALFW) && (i < DSZ - HALFW) &&
                    (j >= HALFW) && (j < DSZ - HALFW) &&
                    (k >= HALFW) && (k < DSZ - HALFW);
    int fin = (interior ? (int)g_valid1[x] : 0) + (int)g_vsum[x];
    int cand = (fin >= 2) ? 1 : 0;
    out[x] = (float)cand;
    float poss = cand ? g_mean1[x] : 0.0f;
    float r = rintf(poss);
    int b = (r <= 0.0f) ? 0 : ((r >= 4095.0f) ? 4095 : (int)r);
    g_bin[x] = (unsigned short)b;
}

// ---------------- zero histogram + grand total ----------------
__global__ void k_zero_hist() {
    int x = blockIdx.x * blockDim.x + threadIdx.x;
    if (x < NBINS) g_hist[x] = 0;
    if (x == 0) g_T[0] = 0.0;
}

// ---------------- histogram (shared + warp-aggregated) ----------------
__global__ void __launch_bounds__(256) k_hist() {
    __shared__ int sh[NBINS];
    for (int b = threadIdx.x; b < NBINS; b += blockDim.x) sh[b] = 0;
    __syncthreads();
    int stride = gridDim.x * blockDim.x;
    for (int x = blockIdx.x * blockDim.x + threadIdx.x; x < NVOX; x += stride) {
        int b = g_bin[x];
        unsigned mask = __activemask();
        unsigned grp  = __match_any_sync(mask, b);
        int leader = __ffs(grp) - 1;
        if ((int)(threadIdx.x & 31) == leader)
            atomicAdd(&sh[b], __popc(grp));
    }
    __syncthreads();
    for (int b = threadIdx.x; b < NBINS; b += blockDim.x) {
        int c = sh[b];
        if (c) atomicAdd(&g_hist[b], c);
    }
}

// ---------------- reciprocal-histogram weights (single block) ----------------
__global__ void __launch_bounds__(1024) k_weights() {
    __shared__ double sh[40];
    int tid  = threadIdx.x;
    int lane = tid & 31;
    int w    = tid >> 5;

    double loc = 0.0;
    for (int b = tid; b < NBINS; b += 1024)
        if (b >= 1) loc += (double)g_hist[b];
    for (int o = 16; o; o >>= 1) loc += __shfl_down_sync(0xffffffffu, loc, o);
    if (lane == 0) sh[w] = loc;
    __syncthreads();
    if (w == 0) {
        double t = (lane < 32) ? sh[lane] : 0.0;
        for (int o = 16; o; o >>= 1) t += __shfl_down_sync(0xffffffffu, t, o);
        if (lane == 0) sh[33] = t;
    }
    __syncthreads();
    float numbf = (float)sh[33];
    __syncthreads();

    double locS = 0.0;
    for (int b = tid; b < NBINS; b += 1024) {
        float rec = 0.0f;
        if (b >= 1) {
            int h = g_hist[b];
            if (h > 0) rec = numbf / (float)h;
        }
        g_ph[b] = rec;
        locS += (double)rec;
    }
    for (int o = 16; o; o >>= 1) locS += __shfl_down_sync(0xffffffffu, locS, o);
    if (lane == 0) sh[w] = locS;
    __syncthreads();
    if (w == 0) {
        double t = (lane < 32) ? sh[lane] : 0.0;
        for (int o = 16; o; o >>= 1) t += __shfl_down_sync(0xffffffffu, t, o);
        if (lane == 0) sh[34] = t;
    }
    __syncthreads();
    float Sf = (float)sh[34];

    for (int b = tid; b < NBINS; b += 1024)
        g_ph[b] = g_ph[b] / Sf;
}

// ---------------- total pw sum ----------------
__global__ void __launch_bounds__(256) k_sumT() {
    int stride = gridDim.x * blockDim.x;
    double loc = 0.0;
    for (int x = blockIdx.x * blockDim.x + threadIdx.x; x < NVOX; x += stride)
        loc += (double)g_ph[g_bin[x]];
    for (int o = 16; o; o >>= 1) loc += __shfl_down_sync(0xffffffffu, loc, o);
    __shared__ double sh[8];
    int lane = threadIdx.x & 31, w = threadIdx.x >> 5;
    if (lane == 0) sh[w] = loc;
    __syncthreads();
    if (w == 0) {
        double t = (lane < 8) ? sh[lane] : 0.0;
        for (int o = 16; o; o >>= 1) t += __shfl_down_sync(0xffffffffu, t, o);
        if (lane == 0) atomicAdd(&g_T[0], t);
    }
}

// ---------------- finalize proba ----------------
__global__ void k_final(float* __restrict__ out) {
    int x = blockIdx.x * blockDim.x + threadIdx.x;
    if (x >= NVOX) return;
    float T = (float)g_T[0];
    out[NVOX + x] = g_ph[g_bin[x]] / T;
}

// ---------------- host orchestration ----------------
extern "C" void kernel_launch(void* const* d_in, const int* in_sizes, int n_in,
                              void* d_out, int out_size) {
    (void)in_sizes; (void)n_in; (void)out_size;
    const float* data = (const float*)d_in[0];
    float* out = (float*)d_out;

    cudaFuncSetAttribute(k_sweep4, cudaFuncAttributeMaxDynamicSharedMemorySize,
                         SWEEP_SMEM);

    const int TPB = 256;
    const int NB  = (NVOX + TPB - 1) / TPB;
    dim3 gSweep(DSZ / TK, DSZ / TJ, DSZ / TI);   // 5 x 10 x 10
    dim3 bTile(32, 16), gTile(DSZ / 32, DSZ);

    // device-symbol addresses resolved at compile time via kernel args
    int* labA; int* labB;
    cudaGetSymbolAddress((void**)&labA, g_labA);
    cudaGetSymbolAddress((void**)&labB, g_labB);

    for (int v = 0; v < 3; ++v) {
        // CCL: 16 sweeps = 4 fused launches; first one builds labels from data.
        // ping-pong: data->B, B->A, A->B, B->A  (final labels in g_labA)
        k_sweep4<<<gSweep, SWEEP_THREADS, SWEEP_SMEM>>>(labA, labB, data, (float)v, 1);
        k_sweep4<<<gSweep, SWEEP_THREADS, SWEEP_SMEM>>>(labB, labA, data, (float)v, 0);
        k_sweep4<<<gSweep, SWEEP_THREADS, SWEEP_SMEM>>>(labA, labB, data, (float)v, 0);
        k_sweep4<<<gSweep, SWEEP_THREADS, SWEEP_SMEM>>>(labB, labA, data, (float)v, 0);

        // component sizes
        k_zero_cnt<<<1024, 256>>>();
        k_count<<<NB, TPB>>>();

        // counts_window = box_sum(seg)  (seg indicator fused into first pass)
        k_boxX_seg<<<D2, DSZ>>>();
        k_boxY<<<gTile, bTile>>>();
        k_boxZ_cw<<<gTile, bTile>>>();        // -> g_cw (int)

        // counts_size = box_sum(lsize * valid); record valid mask
        k_lsv<<<NB, TPB>>>(v);
        k_boxX<<<D2, DSZ>>>();
        k_boxY<<<gTile, bTile>>>();
        k_boxZ_cs<<<gTile, bTile>>>();        // -> g_cs

        if (v == 1)
            k_mean<<<NB, TPB>>>();
    }

    // candidates + bins
    k_candbin<<<NB, TPB>>>(out);

    // probability weights
    k_zero_hist<<<(NBINS + 255) / 256, 256>>>();
    k_hist<<<1024, 256>>>();
    k_weights<<<1, 1024>>>();
    k_sumT<<<1024, 256>>>();
    k_final<<<NB, TPB>>>(out);
}

// round 16
// speedup vs baseline: 2.6701x; 2.4090x over previous
#include <cuda_runtime.h>

#define DSZ   160
#define D2    (DSZ * DSZ)
#define NVOX  (DSZ * DSZ * DSZ)
#define BIGL  (NVOX + 2)
#define NBINS 4096
#define HALFW 16

// fused-sweep tile geometry (v=1 only)
#define TK 32
#define TJ 16
#define TI 8
#define HALO 4
#define RK 40
#define RJ 24
#define RI 16
#define RKP 41
#define KH 20                               // k-cells per thread (split-k = 2)
#define SW_THREADS 768                      // 2 x 24 x 16
#define SW_SMEM ((RI * RJ + 1) * RKP * 4)   // 63140 B (+1 dummy BIG row)

// ---------------- static device scratch ----------------
__device__ int            g_labA[NVOX];
__device__ int            g_labB[NVOX];
__device__ int            g_cnt[NVOX + 1];
__device__ unsigned char  g_k8[3 * NVOX];    // cw k-pass (<=32)
__device__ unsigned short g_j16[3 * NVOX];   // cw j-pass (<=1024)
__device__ unsigned short g_cw[3 * NVOX];    // cw full (<=32768)
__device__ int            g_csk[NVOX];       // cs k-pass
__device__ unsigned       g_csj[NVOX];       // cs j-pass
__device__ float          g_mean1[NVOX];
__device__ unsigned short g_bin[NVOX];
__device__ int            g_hist[NBINS];
__device__ float          g_ph[NBINS];
__device__ double         g_T[1];

// ---------------- fused 4-sweep min-propagation, register-row, split-k ----------------
__global__ void __launch_bounds__(SW_THREADS, 2)
k_sweep4(const int* __restrict__ A, int* __restrict__ B,
         const float* __restrict__ data, int initFlag) {
    extern __shared__ int s[];               // [RI*RJ][RKP] + dummy row
    const int kh = threadIdx.x;              // 0..1
    const int tj = threadIdx.y;              // 0..23
    const int ti = threadIdx.z;              // 0..15
    const int k0 = blockIdx.x * TK;
    const int j0 = blockIdx.y * TJ;
    const int i0 = blockIdx.z * TI;

    int* sRow   = &s[(ti * RJ + tj) * RKP];
    int* sDummy = &s[RI * RJ * RKP];

    // init dummy BIG row (first RKP flat threads)
    {
        int flat = ((ti * RJ + tj) << 1) + kh;
        if (flat < RKP) sDummy[flat] = BIGL;
    }

    int r[KH];
    const int gj  = j0 + tj - HALO;
    const int gi  = i0 + ti - HALO;
    const int gks = k0 - HALO + kh * KH;
    const bool rowIn = (gj >= 0) & (gj < DSZ) & (gi >= 0) & (gi < DSZ);

    if (rowIn & (gks >= 0) & (gks + KH <= DSZ)) {
        const int gb = (gi * DSZ + gj) * DSZ + gks;
        if (initFlag) {
            #pragma unroll
            for (int q = 0; q < KH / 4; ++q) {
                const float4 d = *reinterpret_cast<const float4*>(&data[gb + q * 4]);
                r[q*4+0] = (rintf(d.x) == 1.0f) ? (gb + q*4 + 1) : BIGL;
                r[q*4+1] = (rintf(d.y) == 1.0f) ? (gb + q*4 + 2) : BIGL;
                r[q*4+2] = (rintf(d.z) == 1.0f) ? (gb + q*4 + 3) : BIGL;
                r[q*4+3] = (rintf(d.w) == 1.0f) ? (gb + q*4 + 4) : BIGL;
            }
        } else {
            #pragma unroll
            for (int q = 0; q < KH / 4; ++q) {
                const int4 d = *reinterpret_cast<const int4*>(&A[gb + q * 4]);
                r[q*4+0] = d.x; r[q*4+1] = d.y; r[q*4+2] = d.z; r[q*4+3] = d.w;
            }
        }
    } else {
        #pragma unroll
        for (int c = 0; c < KH; ++c) {
            const int gk = gks + c;
            int val = BIGL;
            if (rowIn && gk >= 0 && gk < DSZ) {
                const int g = (gi * DSZ + gj) * DSZ + gk;
                val = initFlag ? ((rintf(data[g]) == 1.0f) ? (g + 1) : BIGL) : A[g];
            }
            r[c] = val;
        }
    }

    // publish initial
    #pragma unroll
    for (int c = 0; c < KH; ++c) sRow[kh * KH + c] = r[c];

    const int* sJm = (tj > 0)      ? &s[(ti * RJ + tj - 1) * RKP + kh * KH]   : sDummy;
    const int* sJp = (tj < RJ - 1) ? &s[(ti * RJ + tj + 1) * RKP + kh * KH]   : sDummy;
    const int* sIm = (ti > 0)      ? &s[((ti - 1) * RJ + tj) * RKP + kh * KH] : sDummy;
    const int* sIp = (ti < RI - 1) ? &s[((ti + 1) * RJ + tj) * RKP + kh * KH] : sDummy;

    __syncthreads();

    #pragma unroll
    for (int t = 0; t < 4; ++t) {
        const int leftB  = (kh == 0) ? BIGL : sRow[KH - 1];
        const int rightB = (kh == 0) ? sRow[KH] : BIGL;
        int prev = leftB;
        int cur  = r[0];
        #pragma unroll
        for (int c = 0; c < KH; ++c) {
            const int nxt = (c < KH - 1) ? r[c + 1] : rightB;
            int m = BIGL;
            if (cur != BIGL) {
                m = min(min(cur, prev), nxt);
                m = min(m, sJm[c]);
                m = min(m, sJp[c]);
                m = min(m, sIm[c]);
                m = min(m, sIp[c]);
            }
            r[c] = m;
            prev = cur; cur = nxt;
        }
        if (t < 3) {
            __syncthreads();
            #pragma unroll
            for (int c = 0; c < KH; ++c) sRow[kh * KH + c] = r[c];
            __syncthreads();
        }
    }

    // store interior: kh=0 -> c 4..19 (k0..k0+15); kh=1 -> c 0..15 (k0+16..k0+31)
    if (tj >= HALO && tj < RJ - HALO && ti >= HALO && ti < RI - HALO) {
        const int gb = (gi * DSZ + gj) * DSZ + k0 + kh * 16;
        const int c0 = (kh == 0) ? HALO : 0;
        #pragma unroll
        for (int q = 0; q < 4; ++q) {
            int4 d;
            d.x = r[c0 + q*4 + 0]; d.y = r[c0 + q*4 + 1];
            d.z = r[c0 + q*4 + 2]; d.w = r[c0 + q*4 + 3];
            *reinterpret_cast<int4*>(&B[gb + q * 4]) = d;
        }
    }
}

// ---------------- zero component counters (int4) ----------------
__global__ void k_zero_cnt() {
    int stride = gridDim.x * blockDim.x;
    for (int q = blockIdx.x * blockDim.x + threadIdx.x; q < NVOX / 4; q += stride)
        *reinterpret_cast<int4*>(&g_cnt[q * 4]) = make_int4(0, 0, 0, 0);
    if (blockIdx.x == 0 && threadIdx.x == 0) g_cnt[NVOX] = 0;
}

// ---------------- component size count (warp-aggregated atomics) ----------------
__global__ void k_count() {
    int x = blockIdx.x * blockDim.x + threadIdx.x;
    if (x >= NVOX) return;
    int l = g_labA[x];
    unsigned grp = __match_any_sync(0xffffffffu, l);
    int leader = __ffs(grp) - 1;
    if (l != BIGL && (int)(threadIdx.x & 31) == leader)
        atomicAdd(&g_cnt[l], __popc(grp));
}

// ---------------- cw k-pass, all 3 values at once: data -> 3x u8 ----------------
__global__ void __launch_bounds__(DSZ) k_boxX_seg3(const float* __restrict__ data) {
    __shared__ unsigned char s[DSZ];
    int line = blockIdx.x, t = threadIdx.x, base = line * DSZ;
    s[t] = (unsigned char)(int)rintf(data[base + t]);
    __syncthreads();
    int lo = t - HALFW;     if (lo < 0) lo = 0;
    int hi = t + HALFW - 1; if (hi > DSZ - 1) hi = DSZ - 1;
    int a0 = 0, a1 = 0, a2 = 0;
    #pragma unroll 4
    for (int u = lo; u <= hi; ++u) {
        int c = s[u];
        a0 += (c == 0); a1 += (c == 1); a2 += (c == 2);
    }
    g_k8[0 * NVOX + base + t] = (unsigned char)a0;
    g_k8[1 * NVOX + base + t] = (unsigned char)a1;
    g_k8[2 * NVOX + base + t] = (unsigned char)a2;
}

// ---------------- cw j-pass: u8 -> u16, grid.z = value ----------------
__global__ void __launch_bounds__(512) k_boxY3() {
    __shared__ unsigned short s[DSZ][33];
    const unsigned char*  in   = g_k8  + blockIdx.z * NVOX;
    unsigned short*       outp = g_j16 + blockIdx.z * NVOX;
    int kk = threadIdx.x, jj = threadIdx.y;
    int k = blockIdx.x * 32 + kk, i = blockIdx.y;
    int base = i * D2 + k;
    for (int j = jj; j < DSZ; j += 16)
        s[j][kk] = (unsigned short)in[base + j * DSZ];
    __syncthreads();
    for (int j = jj; j < DSZ; j += 16) {
        int lo = j - HALFW;     if (lo < 0) lo = 0;
        int hi = j + HALFW - 1; if (hi > DSZ - 1) hi = DSZ - 1;
        int acc = 0;
        #pragma unroll 4
        for (int t = lo; t <= hi; ++t) acc += s[t][kk];
        outp[base + j * DSZ] = (unsigned short)acc;
    }
}

// ---------------- cw i-pass: u16 -> u16, grid.z = value ----------------
__global__ void __launch_bounds__(512) k_boxZ3() {
    __shared__ unsigned short s[DSZ][33];
    const unsigned short* in   = g_j16 + blockIdx.z * NVOX;
    unsigned short*       outp = g_cw  + blockIdx.z * NVOX;
    int kk = threadIdx.x, ii = threadIdx.y;
    int k = blockIdx.x * 32 + kk, j = blockIdx.y;
    int base = j * DSZ + k;
    for (int i = ii; i < DSZ; i += 16)
        s[i][kk] = in[base + i * D2];
    __syncthreads();
    for (int i = ii; i < DSZ; i += 16) {
        int lo = i - HALFW;     if (lo < 0) lo = 0;
        int hi = i + HALFW - 1; if (hi > DSZ - 1) hi = DSZ - 1;
        int acc = 0;
        #pragma unroll 4
        for (int t = lo; t <= hi; ++t) acc += s[t][kk];
        outp[base + i * D2] = (unsigned short)acc;
    }
}

// ---------------- cs k-pass with fused lsv: labA, cw1, cnt -> int32 ----------------
__global__ void __launch_bounds__(DSZ) k_boxX_cs() {
    __shared__ int s[DSZ];
    int line = blockIdx.x, t = threadIdx.x, base = line * DSZ;
    int lab = g_labA[base + t];
    unsigned short cwv = g_cw[1 * NVOX + base + t];
    s[t] = (lab != BIGL && cwv > 100) ? g_cnt[lab] : 0;
    __syncthreads();
    int lo = t - HALFW;     if (lo < 0) lo = 0;
    int hi = t + HALFW - 1; if (hi > DSZ - 1) hi = DSZ - 1;
    int acc = 0;
    #pragma unroll 4
    for (int u = lo; u <= hi; ++u) acc += s[u];
    g_csk[base + t] = acc;
}

// ---------------- cs j-pass: int32 -> u32 ----------------
__global__ void __launch_bounds__(512) k_boxY_cs() {
    __shared__ unsigned s[DSZ][33];
    int kk = threadIdx.x, jj = threadIdx.y;
    int k = blockIdx.x * 32 + kk, i = blockIdx.y;
    int base = i * D2 + k;
    for (int j = jj; j < DSZ; j += 16)
        s[j][kk] = (unsigned)g_csk[base + j * DSZ];
    __syncthreads();
    for (int j = jj; j < DSZ; j += 16) {
        int lo = j - HALFW;     if (lo < 0) lo = 0;
        int hi = j + HALFW - 1; if (hi > DSZ - 1) hi = DSZ - 1;
        unsigned acc = 0;
        #pragma unroll 4
        for (int t = lo; t <= hi; ++t) acc += s[t][kk];
        g_csj[base + j * DSZ] = acc;
    }
}

// ---------------- cs i-pass fused with mean: u32 -> (u64 accum) -> mean float ----------------
__global__ void __launch_bounds__(512) k_boxZ_mean() {
    __shared__ unsigned s[DSZ][33];
    int kk = threadIdx.x, ii = threadIdx.y;
    int k = blockIdx.x * 32 + kk, j = blockIdx.y;
    int base = j * DSZ + k;
    for (int i = ii; i < DSZ; i += 16)
        s[i][kk] = g_csj[base + i * D2];
    __syncthreads();
    for (int i = ii; i < DSZ; i += 16) {
        int lo = i - HALFW;     if (lo < 0) lo = 0;
        int hi = i + HALFW - 1; if (hi > DSZ - 1) hi = DSZ - 1;
        unsigned long long acc = 0;
        #pragma unroll 4
        for (int t = lo; t <= hi; ++t) acc += (unsigned long long)s[t][kk];
        int x = base + i * D2;
        unsigned short cwv = g_cw[1 * NVOX + x];
        g_mean1[x] = (cwv > 0) ? ((float)acc / (float)cwv) : 0.0f;
    }
}

// ---------------- zero histogram + grand total ----------------
__global__ void k_zero_hist() {
    int x = blockIdx.x * blockDim.x + threadIdx.x;
    if (x < NBINS) g_hist[x] = 0;
    if (x == 0) g_T[0] = 0.0;
}

// ---------------- candidates + bin + fused shared-memory histogram ----------------
__global__ void __launch_bounds__(256) k_candbin_hist(float* __restrict__ out) {
    __shared__ int sh[NBINS];
    for (int b = threadIdx.x; b < NBINS; b += blockDim.x) sh[b] = 0;
    __syncthreads();
    int stride = gridDim.x * blockDim.x;
    for (int x = blockIdx.x * blockDim.x + threadIdx.x; x < NVOX; x += stride) {
        int k = x % DSZ;
        int j = (x / DSZ) % DSZ;
        int i = x / D2;
        bool interior = (i >= HALFW) && (i < DSZ - HALFW) &&
                        (j >= HALFW) && (j < DSZ - HALFW) &&
                        (k >= HALFW) && (k < DSZ - HALFW);
        unsigned short c0 = g_cw[0 * NVOX + x];
        unsigned short c1 = g_cw[1 * NVOX + x];
        unsigned short c2 = g_cw[2 * NVOX + x];
        int fin = ((interior && c1 > 100) ? 1 : 0) + (c0 > 100 ? 1 : 0) + (c2 > 100 ? 1 : 0);
        int cand = (fin >= 2) ? 1 : 0;
        out[x] = (float)cand;
        float poss = cand ? g_mean1[x] : 0.0f;
        float r = rintf(poss);
        int b = (r <= 0.0f) ? 0 : ((r >= 4095.0f) ? 4095 : (int)r);
        g_bin[x] = (unsigned short)b;
        unsigned grp = __match_any_sync(0xffffffffu, b);
        int leader = __ffs(grp) - 1;
        if ((int)(threadIdx.x & 31) == leader)
            atomicAdd(&sh[b], __popc(grp));
    }
    __syncthreads();
    for (int b = threadIdx.x; b < NBINS; b += blockDim.x) {
        int c = sh[b];
        if (c) atomicAdd(&g_hist[b], c);
    }
}

// ---------------- reciprocal-histogram weights (single block) ----------------
__global__ void __launch_bounds__(1024) k_weights() {
    __shared__ double sh[40];
    int tid = threadIdx.x, lane = tid & 31, w = tid >> 5;

    double loc = 0.0;
    for (int b = tid; b < NBINS; b += 1024)
        if (b >= 1) loc += (double)g_hist[b];
    for (int o = 16; o; o >>= 1) loc += __shfl_down_sync(0xffffffffu, loc, o);
    if (lane == 0) sh[w] = loc;
    __syncthreads();
    if (w == 0) {
        double t = (lane < 32) ? sh[lane] : 0.0;
        for (int o = 16; o; o >>= 1) t += __shfl_down_sync(0xffffffffu, t, o);
        if (lane == 0) sh[33] = t;
    }
    __syncthreads();
    float numbf = (float)sh[33];
    __syncthreads();

    double locS = 0.0;
    for (int b = tid; b < NBINS; b += 1024) {
        float rec = 0.0f;
        if (b >= 1) {
            int h = g_hist[b];
            if (h > 0) rec = numbf / (float)h;
        }
        g_ph[b] = rec;
        locS += (double)rec;
    }
    for (int o = 16; o; o >>= 1) locS += __shfl_down_sync(0xffffffffu, locS, o);
    if (lane == 0) sh[w] = locS;
    __syncthreads();
    if (w == 0) {
        double t = (lane < 32) ? sh[lane] : 0.0;
        for (int o = 16; o; o >>= 1) t += __shfl_down_sync(0xffffffffu, t, o);
        if (lane == 0) sh[34] = t;
    }
    __syncthreads();
    float Sf = (float)sh[34];

    for (int b = tid; b < NBINS; b += 1024)
        g_ph[b] = g_ph[b] / Sf;
}

// ---------------- total pw sum ----------------
__global__ void __launch_bounds__(256) k_sumT() {
    int stride = gridDim.x * blockDim.x;
    double loc = 0.0;
    for (int x = blockIdx.x * blockDim.x + threadIdx.x; x < NVOX; x += stride)
        loc += (double)g_ph[g_bin[x]];
    for (int o = 16; o; o >>= 1) loc += __shfl_down_sync(0xffffffffu, loc, o);
    __shared__ double sh[8];
    int lane = threadIdx.x & 31, w = threadIdx.x >> 5;
    if (lane == 0) sh[w] = loc;
    __syncthreads();
    if (w == 0) {
        double t = (lane < 8) ? sh[lane] : 0.0;
        for (int o = 16; o; o >>= 1) t += __shfl_down_sync(0xffffffffu, t, o);
        if (lane == 0) atomicAdd(&g_T[0], t);
    }
}

// ---------------- finalize proba ----------------
__global__ void k_final(float* __restrict__ out) {
    int x = blockIdx.x * blockDim.x + threadIdx.x;
    if (x >= NVOX) return;
    float T = (float)g_T[0];
    out[NVOX + x] = g_ph[g_bin[x]] / T;
}

// ---------------- host orchestration ----------------
extern "C" void kernel_launch(void* const* d_in, const int* in_sizes, int n_in,
                              void* d_out, int out_size) {
    (void)in_sizes; (void)n_in; (void)out_size;
    const float* data = (const float*)d_in[0];
    float* out = (float*)d_out;

    cudaFuncSetAttribute(k_sweep4, cudaFuncAttributeMaxDynamicSharedMemorySize, SW_SMEM);

    const int TPB = 256;
    const int NB  = (NVOX + TPB - 1) / TPB;
    dim3 bSweep(2, RJ, RI);                       // 768
    dim3 gSweep(DSZ / TK, DSZ / TJ, DSZ / TI);    // 5 x 10 x 20
    dim3 bTile(32, 16);
    dim3 gTile3(DSZ / 32, DSZ, 3);
    dim3 gTile1(DSZ / 32, DSZ, 1);

    int* labA; int* labB;
    cudaGetSymbolAddress((void**)&labA, g_labA);
    cudaGetSymbolAddress((void**)&labB, g_labB);

    // CCL for v=1 ONLY (labels for v=0,2 are dead code in the reference).
    // ping-pong: data->B, B->A, A->B, B->A (final labels in g_labA)
    k_sweep4<<<gSweep, bSweep, SW_SMEM>>>(labA, labB, data, 1);
    k_sweep4<<<gSweep, bSweep, SW_SMEM>>>(labB, labA, data, 0);
    k_sweep4<<<gSweep, bSweep, SW_SMEM>>>(labA, labB, data, 0);
    k_sweep4<<<gSweep, bSweep, SW_SMEM>>>(labB, labA, data, 0);

    // component sizes (v=1)
    k_zero_cnt<<<1024, 256>>>();
    k_count<<<NB, TPB>>>();

    // counts_window for all 3 values, batched, narrow types
    k_boxX_seg3<<<D2, DSZ>>>(data);
    k_boxY3<<<gTile3, bTile>>>();
    k_boxZ3<<<gTile3, bTile>>>();

    // counts_size (v=1 only) with fused lsv and fused mean
    k_boxX_cs<<<D2, DSZ>>>();
    k_boxY_cs<<<gTile1, bTile>>>();
    k_boxZ_mean<<<gTile1, bTile>>>();

    // candidates + bins + histogram
    k_zero_hist<<<(NBINS + 255) / 256, 256>>>();
    k_candbin_hist<<<1024, 256>>>(out);

    // probability weights
    k_weights<<<1, 1024>>>();
    k_sumT<<<1024, 256>>>();
    k_final<<<NB, TPB>>>(out);
}